// round 3
// baseline (speedup 1.0000x reference)
#include <cuda_runtime.h>
#include <stdint.h>

#define NN 21824
#define BBATCH 16
#define NCLS 80
#define NBINS 8192
#define CONF_T 0.05f
#define IOU_T 0.5f

typedef unsigned int u32;
typedef unsigned long long u64;

// Scratch (static device globals; no runtime allocation)
__device__ float g_sT[(size_t)BBATCH * NCLS * NN];     // transposed scores [b][c][n]
__device__ float g_cls_s[BBATCH * NCLS * 100];         // per-class top-100 scores
__device__ float g_cls_b[BBATCH * NCLS * 100 * 4];     // per-class top-100 boxes (y1,x1,y2,x2)

// ---------------------------------------------------------------------------
// Kernel 1: fused score compute + transpose.  scores_T[b][c][n] = clf*ctr
// Coalesced read of clfs [b][n][c] tiles, coalesced write of columns.
// ---------------------------------------------------------------------------
__global__ __launch_bounds__(256) void k_transpose(const float* __restrict__ clfs,
                                                   const float* __restrict__ ctrs) {
  int b = blockIdx.y;
  int n0 = blockIdx.x * 32;          // NN = 682*32 exactly
  __shared__ float tile[80][33];
  __shared__ float ctr[32];
  int tid = threadIdx.x;
  if (tid < 32) ctr[tid] = ctrs[b * NN + n0 + tid];
  const float4* src = (const float4*)(clfs + ((size_t)b * NN + n0) * NCLS);
  for (int k4 = tid; k4 < 640; k4 += 256) {   // 32*80/4
    float4 v = src[k4];
    int e = k4 * 4;
    tile[e % 80][e / 80] = v.x; e++;
    tile[e % 80][e / 80] = v.y; e++;
    tile[e % 80][e / 80] = v.z; e++;
    tile[e % 80][e / 80] = v.w;
  }
  __syncthreads();
  for (int k = tid; k < 2560; k += 256) {
    int c = k >> 5, x = k & 31;
    g_sT[((size_t)b * NCLS + c) * NN + n0 + x] = __fmul_rn(tile[c][x], ctr[x]);
  }
}

// ---------------------------------------------------------------------------
// Kernel 2: per-(b,c) top-256 selection + greedy NMS + per-class top-100 out.
// ---------------------------------------------------------------------------
__global__ __launch_bounds__(256) void k_select(const float* __restrict__ regs) {
  const int c = blockIdx.x, b = blockIdx.y;
  const int tid = threadIdx.x;
  const float* col = g_sT + ((size_t)b * NCLS + c) * NN;
  const float4* col4 = (const float4*)col;
  const int N4 = NN / 4;   // 5456

  // 32KB region reused across phases:
  //   Phase A: hist[8192] (u32)
  //   Phase B/C: buf[2048] (u64, bytes [0,16384)) + mask[256][8] (bytes [16384,24576))
  __shared__ char uraw[32768];
  u32* hist = (u32*)uraw;
  u64* buf = (u64*)uraw;
  u32(*mask)[8] = (u32(*)[8])(uraw + 16384);

  __shared__ float by1[256], bx1[256], by2[256], bx2[256], bar[256], bsc[256];
  __shared__ u32 chs[257];
  __shared__ u32 validw[8], keepw[8];
  __shared__ int s_tstar, s_V;
  __shared__ int warpcnt[8];

  // ---- Phase A: histogram of score bits (>>17), scores > CONF only ----
  for (int i = tid; i < NBINS; i += 256) hist[i] = 0u;
  if (tid == 0) { s_tstar = NBINS; s_V = 0; }
  __syncthreads();

  for (int i = tid; i < N4; i += 256) {
    float4 v = col4[i];
    if (v.x > CONF_T) atomicAdd(&hist[__float_as_uint(v.x) >> 17], 1u);
    if (v.y > CONF_T) atomicAdd(&hist[__float_as_uint(v.y) >> 17], 1u);
    if (v.z > CONF_T) atomicAdd(&hist[__float_as_uint(v.z) >> 17], 1u);
    if (v.w > CONF_T) atomicAdd(&hist[__float_as_uint(v.w) >> 17], 1u);
  }
  __syncthreads();

  // Suffix scan to find threshold bin t*: largest t with count(bin>=t) >= target
  u32 csum = 0;
  const int b0 = tid * 32;
  for (int i = 0; i < 32; i++) csum += hist[b0 + i];
  chs[tid] = csum;
  __syncthreads();
  if (tid == 0) {
    u32 run = 0;
    for (int i = 255; i >= 0; i--) { u32 t = chs[i]; chs[i] = run; run += t; }
    chs[256] = run;
  }
  __syncthreads();
  const u32 total = chs[256];
  const u32 target = total < 256u ? total : 256u;
  if (target > 0) {
    u32 running = chs[tid];
    for (int bi = b0 + 31; bi >= b0; bi--) {
      u32 cv = hist[bi];
      running += cv;
      if (running >= target && running - cv < target) s_tstar = bi;  // unique bin
    }
  }
  __syncthreads();
  const int tstar = s_tstar;

  // ---- Phase B: collect candidates >= threshold bin, then stable sort ----
  for (int i = tid; i < N4; i += 256) {
    float4 v = col4[i];
    float e[4] = {v.x, v.y, v.z, v.w};
#pragma unroll
    for (int j = 0; j < 4; j++) {
      float s = e[j];
      u32 sb = __float_as_uint(s);
      if (s > CONF_T && (int)(sb >> 17) >= tstar) {
        int p = atomicAdd(&s_V, 1);
        if (p < 2048)
          buf[p] = ((u64)sb << 32) | (u64)(0xFFFFFFFFu - (u32)(i * 4 + j));
      }
    }
  }
  __syncthreads();
  int V = s_V; if (V > 2048) V = 2048;
  const int M = (V <= 512) ? 512 : (V <= 1024 ? 1024 : 2048);
  for (int i = V + tid; i < M; i += 256) buf[i] = 0ull;
  __syncthreads();

  // Bitonic sort descending on 64-bit keys (stable: low bits = ~index)
  for (int k = 2; k <= M; k <<= 1) {
    for (int j = k >> 1; j > 0; j >>= 1) {
      for (int i = tid; i < M; i += 256) {
        int l = i ^ j;
        if (l > i) {
          u64 a = buf[i], bb2 = buf[l];
          bool up = ((i & k) == 0);
          if (up ? (a < bb2) : (a > bb2)) { buf[i] = bb2; buf[l] = a; }
        }
      }
      __syncthreads();
    }
  }

  // ---- Extract 256 candidates, decode boxes ----
  u64 key = buf[tid];
  float sc = __uint_as_float((u32)(key >> 32));
  bool valid = sc > CONF_T;
  bsc[tid] = sc;
  float y1 = 0.f, x1 = 0.f, y2 = 0.f, x2 = 0.f;
  if (valid) {
    int n = (int)(0xFFFFFFFFu - (u32)key);
    int off, g, lvl;
    if (n < 16384)      { lvl = 0; off = 0;     g = 7; }
    else if (n < 20480) { lvl = 1; off = 16384; g = 6; }
    else if (n < 21504) { lvl = 2; off = 20480; g = 5; }
    else if (n < 21760) { lvl = 3; off = 21504; g = 4; }
    else                { lvl = 4; off = 21760; g = 3; }
    int m = n - off;
    float gx = (float)(m >> g);              // meshgrid 'xy': x is the major axis
    float gy = (float)(m & ((1 << g) - 1));
    float sv = (float)(8 << lvl);
    float4 r = ((const float4*)regs)[(size_t)b * NN + n];
    y1 = __fmul_rn(gy - r.z, sv);
    x1 = __fmul_rn(gx - r.x, sv);
    y2 = __fmul_rn(gy + r.w, sv);
    x2 = __fmul_rn(gx + r.y, sv);
  }
  by1[tid] = y1; bx1[tid] = x1; by2[tid] = y2; bx2[tid] = x2;
  bar[tid] = __fmul_rn(y2 - y1, x2 - x1);
  u32 vb = __ballot_sync(0xFFFFFFFFu, valid);
  if ((tid & 31) == 0) validw[tid >> 5] = vb;
  __syncthreads();

  // ---- Phase C: suppression bitmask (j > i, iou > 0.5) ----
  {
    const int i = tid;
    float iy1 = by1[i], ix1 = bx1[i], iy2 = by2[i], ix2 = bx2[i], ia = bar[i];
#pragma unroll
    for (int w = 0; w < 8; w++) {
      u32 bits = 0;
      if (w * 32 + 31 > i) {
        for (int jj = 0; jj < 32; jj++) {
          int j = w * 32 + jj;
          if (j > i) {
            float ih = fminf(iy2, by2[j]) - fmaxf(iy1, by1[j]);
            float iw = fminf(ix2, bx2[j]) - fmaxf(ix1, bx1[j]);
            ih = fmaxf(ih, 0.f); iw = fmaxf(iw, 0.f);
            float inter = __fmul_rn(ih, iw);
            float uni = ia + bar[j] - inter;
            float iou = inter / fmaxf(uni, 1e-8f);
            if (iou > IOU_T) bits |= (1u << jj);
          }
        }
      }
      mask[i][w] = bits;
    }
  }
  __syncthreads();

  // ---- Greedy scan (single thread, keep bits in registers) ----
  if (tid == 0) {
    u32 kw[8];
#pragma unroll
    for (int w = 0; w < 8; w++) kw[w] = validw[w];
#pragma unroll
    for (int w = 0; w < 8; w++) {
      for (int bit = 0; bit < 32; bit++) {
        if ((kw[w] >> bit) & 1u) {
          const uint4* mr = (const uint4*)&mask[w * 32 + bit][0];
          uint4 m0 = mr[0], m1 = mr[1];
          kw[0] &= ~m0.x; kw[1] &= ~m0.y; kw[2] &= ~m0.z; kw[3] &= ~m0.w;
          kw[4] &= ~m1.x; kw[5] &= ~m1.y; kw[6] &= ~m1.z; kw[7] &= ~m1.w;
        }
      }
    }
#pragma unroll
    for (int w = 0; w < 8; w++) keepw[w] = kw[w];
  }
  __syncthreads();

  // ---- Compact survivors (already score-descending) into per-class top-100 ----
  bool kept = (keepw[tid >> 5] >> (tid & 31)) & 1u;
  u32 kb = __ballot_sync(0xFFFFFFFFu, kept);
  int lane = tid & 31, wid = tid >> 5;
  if (lane == 0) warpcnt[wid] = __popc(kb);
  __syncthreads();
  int base = 0;
  for (int w = 0; w < wid; w++) base += warpcnt[w];
  int rank = base + __popc(kb & ((1u << lane) - 1u));

  float* ocs = g_cls_s + ((size_t)b * NCLS + c) * 100;
  float* ocb = g_cls_b + ((size_t)b * NCLS + c) * 400;
  for (int i = tid; i < 100; i += 256) ocs[i] = 0.f;
  for (int i = tid; i < 400; i += 256) ocb[i] = 0.f;
  __syncthreads();
  if (kept && rank < 100) {
    ocs[rank] = bsc[tid];
    ocb[rank * 4 + 0] = by1[tid];
    ocb[rank * 4 + 1] = bx1[tid];
    ocb[rank * 4 + 2] = by2[tid];
    ocb[rank * 4 + 3] = bx2[tid];
  }
}

// ---------------------------------------------------------------------------
// Kernel 3: per-batch stable top-100 of 80*100 = 8000 (bitonic over 8192)
// ---------------------------------------------------------------------------
__global__ __launch_bounds__(1024) void k_final(float* __restrict__ out) {
  extern __shared__ u64 sk[];
  int b = blockIdx.x, tid = threadIdx.x;
  const float* cs = g_cls_s + (size_t)b * 8000;
  for (int i = tid; i < 8192; i += 1024) {
    u64 key = 0ull;
    if (i < 8000)
      key = ((u64)__float_as_uint(cs[i]) << 32) | (u64)(0xFFFFFFFFu - (u32)i);
    sk[i] = key;
  }
  __syncthreads();
  for (int k = 2; k <= 8192; k <<= 1) {
    for (int j = k >> 1; j > 0; j >>= 1) {
      for (int i = tid; i < 8192; i += 1024) {
        int l = i ^ j;
        if (l > i) {
          u64 a = sk[i], b2 = sk[l];
          bool up = ((i & k) == 0);
          if (up ? (a < b2) : (a > b2)) { sk[i] = b2; sk[l] = a; }
        }
      }
      __syncthreads();
    }
  }
  if (tid < 100) {
    u64 key = sk[tid];
    float s = __uint_as_float((u32)(key >> 32));
    int flat = (int)(0xFFFFFFFFu - (u32)key);
    if (flat < 0 || flat >= 8000) { flat = 0; s = 0.f; }  // unreachable guard
    float mlt = (s > 0.f) ? 1.f : 0.f;
    const float* bx = g_cls_b + ((size_t)b * 8000 + flat) * 4;
    out[(b * 100 + tid) * 4 + 0] = bx[0] * mlt;
    out[(b * 100 + tid) * 4 + 1] = bx[1] * mlt;
    out[(b * 100 + tid) * 4 + 2] = bx[2] * mlt;
    out[(b * 100 + tid) * 4 + 3] = bx[3] * mlt;
    out[6400 + b * 100 + tid] = (float)(flat / 100);
    out[8000 + b * 100 + tid] = s;
  }
}

// ---------------------------------------------------------------------------
extern "C" void kernel_launch(void* const* d_in, const int* in_sizes, int n_in,
                              void* d_out, int out_size) {
  // Defensive pointer remap by element count
  const float* regs = (const float*)d_in[0];
  const float* ctrs = (const float*)d_in[1];
  const float* clfs = (const float*)d_in[2];
  for (int i = 0; i < n_in; i++) {
    if (in_sizes[i] == BBATCH * NN * 4) regs = (const float*)d_in[i];
    else if (in_sizes[i] == BBATCH * NN) ctrs = (const float*)d_in[i];
    else if (in_sizes[i] == BBATCH * NN * NCLS) clfs = (const float*)d_in[i];
  }
  float* out = (float*)d_out;

  dim3 gT(NN / 32, BBATCH);
  k_transpose<<<gT, 256>>>(clfs, ctrs);

  dim3 gS(NCLS, BBATCH);
  k_select<<<gS, 256>>>(regs);

  cudaFuncSetAttribute(k_final, cudaFuncAttributeMaxDynamicSharedMemorySize, 65536);
  k_final<<<BBATCH, 1024, 65536>>>(out);
}

// round 7
// speedup vs baseline: 1.0472x; 1.0472x over previous
#include <cuda_runtime.h>
#include <stdint.h>

#define NN 21824
#define BBATCH 16
#define NCLS 80
#define CONF_T 0.05f
#define IOU_T 0.5f

typedef unsigned short u16;
typedef unsigned int u32;
typedef unsigned long long u64;

// k_select dynamic shared layout
#define SARR_BYTES 43648              // NN u16 keys
#define BUF_OFF    43648              // 2048 u64 sort buffer
#define DYN_TOTAL  (43648 + 16384)    // 60032 B

// Binary-search bounds for key16 thresholds: scores in (CONF, 2.0)
// key16(0.05) = 0x3D4C = 15692 -> lo = 7846 (T=15692: count==total always)
// score < 2.0 -> key16 < 0x4000 = 16384 -> hi = 8192 (T=16384: count==0)
#define BS_LO 7846
#define BS_HI 8192

// Scratch (static device globals; no runtime allocation)
__device__ u16 g_keys[(size_t)BBATCH * NCLS * NN];     // 16-bit score keys [b][c][n]
__device__ float g_cls_s[BBATCH * NCLS * 100];         // per-class top-100 scores
__device__ float g_cls_b[BBATCH * NCLS * 100 * 4];     // per-class top-100 boxes

// ---------------------------------------------------------------------------
// Kernel 1: fused score compute + transpose -> 16-bit keys.
// key16[b][c][n] = (clf*ctr > CONF) ? bits(clf*ctr)>>16 : 0
// ---------------------------------------------------------------------------
__global__ __launch_bounds__(256) void k_transpose(const float* __restrict__ clfs,
                                                   const float* __restrict__ ctrs) {
  int b = blockIdx.y;
  int n0 = blockIdx.x * 32;          // NN = 682*32 exactly
  __shared__ float tile[80][33];
  __shared__ float ctr[32];
  int tid = threadIdx.x;
  if (tid < 32) ctr[tid] = ctrs[b * NN + n0 + tid];
  const float4* src = (const float4*)(clfs + ((size_t)b * NN + n0) * NCLS);
  for (int k4 = tid; k4 < 640; k4 += 256) {   // 32*80/4
    float4 v = src[k4];
    int e = k4 * 4;
    tile[e % 80][e / 80] = v.x; e++;
    tile[e % 80][e / 80] = v.y; e++;
    tile[e % 80][e / 80] = v.z; e++;
    tile[e % 80][e / 80] = v.w;
  }
  __syncthreads();
  // 80 classes x 16 u32 (32 u16 keys) per block
  for (int k = tid; k < 1280; k += 256) {
    int c = k >> 4, x = (k & 15) * 2;
    float s0 = __fmul_rn(tile[c][x], ctr[x]);
    float s1 = __fmul_rn(tile[c][x + 1], ctr[x + 1]);
    u32 k0 = s0 > CONF_T ? (__float_as_uint(s0) >> 16) : 0u;
    u32 k1 = s1 > CONF_T ? (__float_as_uint(s1) >> 16) : 0u;
    u32* dst = (u32*)(g_keys + ((size_t)b * NCLS + c) * NN + n0);
    dst[k & 15] = k0 | (k1 << 16);
  }
}

// ---------------------------------------------------------------------------
// Kernel 2: per-(b,c) top-256 selection (atomic-free threshold search)
//           + greedy NMS + per-class top-100 out.
// ---------------------------------------------------------------------------
__global__ __launch_bounds__(256) void k_select(const float* __restrict__ regs,
                                                const float* __restrict__ clfs,
                                                const float* __restrict__ ctrs) {
  const int c = blockIdx.x, b = blockIdx.y;
  const int tid = threadIdx.x;
  const int lane = tid & 31, wid = tid >> 5;

  extern __shared__ __align__(16) char dyn[];
  u32* sarr = (u32*)dyn;                       // NN u16 keys (as u32 pairs)
  u64* buf = (u64*)(dyn + BUF_OFF);            // 2048 u64
  u32(*mask)[8] = (u32(*)[8])dyn;              // overlays sarr (dead after collect)

  __shared__ float by1[256], bx1[256], by2[256], bx2[256], bar[256], bsc[256];
  __shared__ u32 validw[8], keepw[8];
  __shared__ int s_cnt, s_V;
  __shared__ int warpcnt[8];

  float* ocs = g_cls_s + ((size_t)b * NCLS + c) * 100;
  float* ocb = g_cls_b + ((size_t)b * NCLS + c) * 400;

  if (tid == 0) { s_cnt = 0; s_V = 0; }

  // ---- Phase A: copy key column into shared + count nonzero ----
  const uint4* gk4 = (const uint4*)(g_keys + (size_t)(b * NCLS + c) * NN);
  uint4* sk4 = (uint4*)sarr;
  int cl = 0;
  for (int i = tid; i < NN / 8; i += 256) {
    uint4 w = gk4[i];
    sk4[i] = w;
    cl += ((w.x & 0xFFFFu) != 0u) + ((w.x >> 16) != 0u)
        + ((w.y & 0xFFFFu) != 0u) + ((w.y >> 16) != 0u)
        + ((w.z & 0xFFFFu) != 0u) + ((w.z >> 16) != 0u)
        + ((w.w & 0xFFFFu) != 0u) + ((w.w >> 16) != 0u);
  }
  __syncthreads();
  for (int o = 16; o; o >>= 1) cl += __shfl_down_sync(0xFFFFFFFFu, cl, o);
  if (lane == 0 && cl) atomicAdd(&s_cnt, cl);
  __syncthreads();
  const int total = s_cnt;
  const int target = total < 256 ? total : 256;

  if (target == 0) {
    for (int i = tid; i < 100; i += 256) ocs[i] = 0.f;
    for (int i = tid; i < 400; i += 256) ocb[i] = 0.f;
    return;
  }

  // ---- Binary search largest t with count(key16 >= 2t) >= target ----
  const uint4* sa4 = (const uint4*)sarr;
  int lo = BS_LO, hi = BS_HI;
  while (hi - lo > 1) {
    int mid = (lo + hi) >> 1;
    u32 T = (u32)(2 * mid);
    __syncthreads();
    if (tid == 0) s_cnt = 0;
    __syncthreads();
    int cc = 0;
    for (int i = tid; i < NN / 8; i += 256) {
      uint4 w = sa4[i];
      cc += ((w.x & 0xFFFFu) >= T) + ((w.x >> 16) >= T)
          + ((w.y & 0xFFFFu) >= T) + ((w.y >> 16) >= T)
          + ((w.z & 0xFFFFu) >= T) + ((w.z >> 16) >= T)
          + ((w.w & 0xFFFFu) >= T) + ((w.w >> 16) >= T);
    }
    for (int o = 16; o; o >>= 1) cc += __shfl_down_sync(0xFFFFFFFFu, cc, o);
    if (lane == 0 && cc) atomicAdd(&s_cnt, cc);
    __syncthreads();
    if (s_cnt >= target) lo = mid; else hi = mid;
  }
  const u32 T2 = (u32)(2 * lo);

  // ---- Collect candidates; recompute exact 32-bit score = fmul(clf, ctr) ----
  const float* clfb = clfs + (size_t)b * NN * NCLS + c;
  const float* ctrb = ctrs + (size_t)b * NN;
  for (int j = tid; j < NN / 2; j += 256) {
    u32 w = sarr[j];
    u32 klo = w & 0xFFFFu, khi = w >> 16;
    if (klo >= T2) {
      int n = 2 * j;
      u32 sb = __float_as_uint(__fmul_rn(clfb[(size_t)n * NCLS], ctrb[n]));
      int p = atomicAdd(&s_V, 1);
      if (p < 2048) buf[p] = ((u64)sb << 32) | (u64)(0xFFFFFFFFu - (u32)n);
    }
    if (khi >= T2) {
      int n = 2 * j + 1;
      u32 sb = __float_as_uint(__fmul_rn(clfb[(size_t)n * NCLS], ctrb[n]));
      int p = atomicAdd(&s_V, 1);
      if (p < 2048) buf[p] = ((u64)sb << 32) | (u64)(0xFFFFFFFFu - (u32)n);
    }
  }
  __syncthreads();
  int V = s_V; if (V > 2048) V = 2048;
  const int M = (V <= 512) ? 512 : (V <= 1024 ? 1024 : 2048);
  for (int i = V + tid; i < M; i += 256) buf[i] = 0ull;
  __syncthreads();

  // Bitonic sort descending on 64-bit keys (stable: low bits = ~index)
  for (int k = 2; k <= M; k <<= 1) {
    for (int j = k >> 1; j > 0; j >>= 1) {
      for (int i = tid; i < M; i += 256) {
        int l = i ^ j;
        if (l > i) {
          u64 a = buf[i], bb2 = buf[l];
          bool up = ((i & k) == 0);
          if (up ? (a < bb2) : (a > bb2)) { buf[i] = bb2; buf[l] = a; }
        }
      }
      __syncthreads();
    }
  }

  // ---- Extract 256 candidates, decode boxes ----
  u64 key = buf[tid];
  float sc = __uint_as_float((u32)(key >> 32));
  bool valid = sc > CONF_T;
  bsc[tid] = sc;
  float y1 = 0.f, x1 = 0.f, y2 = 0.f, x2 = 0.f;
  if (valid) {
    int n = (int)(0xFFFFFFFFu - (u32)key);
    int off, g, lvl;
    if (n < 16384)      { lvl = 0; off = 0;     g = 7; }
    else if (n < 20480) { lvl = 1; off = 16384; g = 6; }
    else if (n < 21504) { lvl = 2; off = 20480; g = 5; }
    else if (n < 21760) { lvl = 3; off = 21504; g = 4; }
    else                { lvl = 4; off = 21760; g = 3; }
    int m = n - off;
    float gx = (float)(m >> g);              // meshgrid 'xy': x is the major axis
    float gy = (float)(m & ((1 << g) - 1));
    float sv = (float)(8 << lvl);
    float4 r = ((const float4*)regs)[(size_t)b * NN + n];
    y1 = __fmul_rn(gy - r.z, sv);
    x1 = __fmul_rn(gx - r.x, sv);
    y2 = __fmul_rn(gy + r.w, sv);
    x2 = __fmul_rn(gx + r.y, sv);
  }
  by1[tid] = y1; bx1[tid] = x1; by2[tid] = y2; bx2[tid] = x2;
  bar[tid] = __fmul_rn(y2 - y1, x2 - x1);
  u32 vb = __ballot_sync(0xFFFFFFFFu, valid);
  if (lane == 0) validw[wid] = vb;
  __syncthreads();

  // ---- Suppression bitmask (j > i, iou > 0.5; exact IEEE divide) ----
  {
    const int i = tid;
    float iy1 = by1[i], ix1 = bx1[i], iy2 = by2[i], ix2 = bx2[i], ia = bar[i];
#pragma unroll
    for (int w = 0; w < 8; w++) {
      u32 bits = 0;
      if (w * 32 + 31 > i) {
        for (int jj = 0; jj < 32; jj++) {
          int j = w * 32 + jj;
          if (j > i) {
            float ih = fminf(iy2, by2[j]) - fmaxf(iy1, by1[j]);
            float iw = fminf(ix2, bx2[j]) - fmaxf(ix1, bx1[j]);
            ih = fmaxf(ih, 0.f); iw = fmaxf(iw, 0.f);
            float inter = __fmul_rn(ih, iw);
            float uni = ia + bar[j] - inter;
            float iou = inter / fmaxf(uni, 1e-8f);
            if (iou > IOU_T) bits |= (1u << jj);
          }
        }
      }
      mask[i][w] = bits;
    }
  }
  __syncthreads();

  // ---- Greedy scan (single thread, keep bits in registers) ----
  if (tid == 0) {
    u32 kw[8];
#pragma unroll
    for (int w = 0; w < 8; w++) kw[w] = validw[w];
#pragma unroll
    for (int w = 0; w < 8; w++) {
      for (int bit = 0; bit < 32; bit++) {
        if ((kw[w] >> bit) & 1u) {
          const uint4* mr = (const uint4*)&mask[w * 32 + bit][0];
          uint4 m0 = mr[0], m1 = mr[1];
          kw[0] &= ~m0.x; kw[1] &= ~m0.y; kw[2] &= ~m0.z; kw[3] &= ~m0.w;
          kw[4] &= ~m1.x; kw[5] &= ~m1.y; kw[6] &= ~m1.z; kw[7] &= ~m1.w;
        }
      }
    }
#pragma unroll
    for (int w = 0; w < 8; w++) keepw[w] = kw[w];
  }
  __syncthreads();

  // ---- Compact survivors (score-descending) into per-class top-100 ----
  bool kept = (keepw[wid] >> lane) & 1u;
  u32 kb = __ballot_sync(0xFFFFFFFFu, kept);
  if (lane == 0) warpcnt[wid] = __popc(kb);
  __syncthreads();
  int base = 0;
  for (int w = 0; w < wid; w++) base += warpcnt[w];
  int rank = base + __popc(kb & ((1u << lane) - 1u));

  for (int i = tid; i < 100; i += 256) ocs[i] = 0.f;
  for (int i = tid; i < 400; i += 256) ocb[i] = 0.f;
  __syncthreads();
  if (kept && rank < 100) {
    ocs[rank] = bsc[tid];
    ocb[rank * 4 + 0] = by1[tid];
    ocb[rank * 4 + 1] = bx1[tid];
    ocb[rank * 4 + 2] = by2[tid];
    ocb[rank * 4 + 3] = bx2[tid];
  }
}

// ---------------------------------------------------------------------------
// Kernel 3: per-batch stable top-100 of 8000 via threshold search + small sort
// ---------------------------------------------------------------------------
__global__ __launch_bounds__(256) void k_final(float* __restrict__ out) {
  int b = blockIdx.x, tid = threadIdx.x;
  const int lane = tid & 31;
  __shared__ __align__(16) u32 skeys[4000];   // 8000 u16 keys
  __shared__ u64 fbuf[1024];
  __shared__ int s_cnt, s_V;
  const float* cs = g_cls_s + (size_t)b * 8000;

  if (tid == 0) { s_cnt = 0; s_V = 0; }
  const float2* cs2 = (const float2*)cs;
  int cl = 0;
  for (int i = tid; i < 4000; i += 256) {
    float2 v = cs2[i];
    u32 k0 = v.x > 0.f ? (__float_as_uint(v.x) >> 16) : 0u;
    u32 k1 = v.y > 0.f ? (__float_as_uint(v.y) >> 16) : 0u;
    skeys[i] = k0 | (k1 << 16);
    cl += (k0 != 0u) + (k1 != 0u);
  }
  __syncthreads();
  for (int o = 16; o; o >>= 1) cl += __shfl_down_sync(0xFFFFFFFFu, cl, o);
  if (lane == 0 && cl) atomicAdd(&s_cnt, cl);
  __syncthreads();
  const int total = s_cnt;
  const int target = total < 100 ? total : 100;

  u32 T2 = 0;
  if (target > 0) {
    const uint4* sa4 = (const uint4*)skeys;
    int lo = BS_LO, hi = BS_HI;   // kept scores are 0 or in (CONF, 1)
    while (hi - lo > 1) {
      int mid = (lo + hi) >> 1;
      u32 T = (u32)(2 * mid);
      __syncthreads();
      if (tid == 0) s_cnt = 0;
      __syncthreads();
      int cc = 0;
      for (int i = tid; i < 1000; i += 256) {
        uint4 w = sa4[i];
        cc += ((w.x & 0xFFFFu) >= T) + ((w.x >> 16) >= T)
            + ((w.y & 0xFFFFu) >= T) + ((w.y >> 16) >= T)
            + ((w.z & 0xFFFFu) >= T) + ((w.z >> 16) >= T)
            + ((w.w & 0xFFFFu) >= T) + ((w.w >> 16) >= T);
      }
      for (int o = 16; o; o >>= 1) cc += __shfl_down_sync(0xFFFFFFFFu, cc, o);
      if (lane == 0 && cc) atomicAdd(&s_cnt, cc);
      __syncthreads();
      if (s_cnt >= target) lo = mid; else hi = mid;
    }
    T2 = (u32)(2 * lo);

    for (int j = tid; j < 4000; j += 256) {
      u32 w = skeys[j];
      u32 klo = w & 0xFFFFu, khi = w >> 16;
      if (klo >= T2) {
        int n = 2 * j;
        int p = atomicAdd(&s_V, 1);
        if (p < 1024)
          fbuf[p] = ((u64)__float_as_uint(cs[n]) << 32) | (u64)(0xFFFFFFFFu - (u32)n);
      }
      if (khi >= T2) {
        int n = 2 * j + 1;
        int p = atomicAdd(&s_V, 1);
        if (p < 1024)
          fbuf[p] = ((u64)__float_as_uint(cs[n]) << 32) | (u64)(0xFFFFFFFFu - (u32)n);
      }
    }
  }
  // If fewer than 100 positives, fill with lowest-index zero-score slots
  // (stable tie behavior: zeros in [0,256) suffice since >=156 are zero there).
  if (total < 100) {
    int i = tid;  // 256 threads cover flat indices [0,256)
    if (cs[i] == 0.f) {
      int p = atomicAdd(&s_V, 1);
      if (p < 1024) fbuf[p] = (u64)(0xFFFFFFFFu - (u32)i);
    }
  }
  __syncthreads();
  int V = s_V; if (V > 1024) V = 1024;
  const int M = (V <= 128) ? 128 : (V <= 256 ? 256 : (V <= 512 ? 512 : 1024));
  for (int i = V + tid; i < M; i += 256) fbuf[i] = 0ull;
  __syncthreads();

  for (int k = 2; k <= M; k <<= 1) {
    for (int j = k >> 1; j > 0; j >>= 1) {
      for (int i = tid; i < M; i += 256) {
        int l = i ^ j;
        if (l > i) {
          u64 a = fbuf[i], b2 = fbuf[l];
          bool up = ((i & k) == 0);
          if (up ? (a < b2) : (a > b2)) { fbuf[i] = b2; fbuf[l] = a; }
        }
      }
      __syncthreads();
    }
  }

  if (tid < 100) {
    u64 key = fbuf[tid];
    float s = __uint_as_float((u32)(key >> 32));
    int flat = (int)(0xFFFFFFFFu - (u32)key);
    if (flat < 0 || flat >= 8000) { flat = 0; s = 0.f; }  // guard (padding keys)
    float mlt = (s > 0.f) ? 1.f : 0.f;
    const float* bx = g_cls_b + ((size_t)b * 8000 + flat) * 4;
    out[(b * 100 + tid) * 4 + 0] = bx[0] * mlt;
    out[(b * 100 + tid) * 4 + 1] = bx[1] * mlt;
    out[(b * 100 + tid) * 4 + 2] = bx[2] * mlt;
    out[(b * 100 + tid) * 4 + 3] = bx[3] * mlt;
    out[6400 + b * 100 + tid] = (float)(flat / 100);
    out[8000 + b * 100 + tid] = s;
  }
}

// ---------------------------------------------------------------------------
extern "C" void kernel_launch(void* const* d_in, const int* in_sizes, int n_in,
                              void* d_out, int out_size) {
  const float* regs = (const float*)d_in[0];
  const float* ctrs = (const float*)d_in[1];
  const float* clfs = (const float*)d_in[2];
  for (int i = 0; i < n_in; i++) {
    if (in_sizes[i] == BBATCH * NN * 4) regs = (const float*)d_in[i];
    else if (in_sizes[i] == BBATCH * NN) ctrs = (const float*)d_in[i];
    else if (in_sizes[i] == BBATCH * NN * NCLS) clfs = (const float*)d_in[i];
  }
  float* out = (float*)d_out;

  dim3 gT(NN / 32, BBATCH);
  k_transpose<<<gT, 256>>>(clfs, ctrs);

  cudaFuncSetAttribute(k_select, cudaFuncAttributeMaxDynamicSharedMemorySize, DYN_TOTAL);
  dim3 gS(NCLS, BBATCH);
  k_select<<<gS, 256, DYN_TOTAL>>>(regs, clfs, ctrs);

  k_final<<<BBATCH, 256>>>(out);
}

// round 11
// speedup vs baseline: 1.1220x; 1.0714x over previous
#include <cuda_runtime.h>
#include <stdint.h>

#define NN 21824
#define BBATCH 16
#define NCLS 80
#define CONF_T 0.05f
#define IOU_T 0.5f

typedef unsigned short u16;
typedef unsigned int u32;
typedef unsigned long long u64;

// key16 range for scores in (CONF, 2): [0x3D4C, 0x4000) -> bins (key>>1)-7846 in [0,346)
#define BIN_BASE 7846
#define HBINS 512

// k_final binary-search bounds
#define BS_LO 7846
#define BS_HI 8192

// Scratch (static device globals; no runtime allocation)
__device__ __align__(16) u16 g_keys[(size_t)BBATCH * NCLS * NN];  // 16-bit score keys [b][c][n]
__device__ float g_cls_s[BBATCH * NCLS * 100];          // per-class top-100 scores
__device__ float g_cls_b[BBATCH * NCLS * 100 * 4];      // per-class top-100 boxes

// ---------------------------------------------------------------------------
// Kernel 1: fused score compute + transpose -> 16-bit keys.
// key16[b][c][n] = (clf*ctr > CONF) ? bits(clf*ctr)>>16 : 0
// ---------------------------------------------------------------------------
__global__ __launch_bounds__(256) void k_transpose(const float* __restrict__ clfs,
                                                   const float* __restrict__ ctrs) {
  int b = blockIdx.y;
  int n0 = blockIdx.x * 32;          // NN = 682*32 exactly
  __shared__ float tile[80][33];
  __shared__ float ctr[32];
  int tid = threadIdx.x;
  if (tid < 32) ctr[tid] = ctrs[b * NN + n0 + tid];
  const float4* src = (const float4*)(clfs + ((size_t)b * NN + n0) * NCLS);
  for (int k4 = tid; k4 < 640; k4 += 256) {   // 32*80/4
    float4 v = src[k4];
    int x = k4 / 20, c = (k4 % 20) * 4;       // e = 4*k4; c = e%80 (no wrap), x = e/80
    tile[c][x] = v.x;
    tile[c + 1][x] = v.y;
    tile[c + 2][x] = v.z;
    tile[c + 3][x] = v.w;
  }
  __syncthreads();
  // 80 classes x 16 u32 (32 u16 keys) per block
  for (int k = tid; k < 1280; k += 256) {
    int c = k >> 4, x = (k & 15) * 2;
    float s0 = __fmul_rn(tile[c][x], ctr[x]);
    float s1 = __fmul_rn(tile[c][x + 1], ctr[x + 1]);
    u32 k0 = s0 > CONF_T ? (__float_as_uint(s0) >> 16) : 0u;
    u32 k1 = s1 > CONF_T ? (__float_as_uint(s1) >> 16) : 0u;
    u32* dst = (u32*)(g_keys + ((size_t)b * NCLS + c) * NN + n0);
    dst[k & 15] = k0 | (k1 << 16);
  }
}

// ---------------------------------------------------------------------------
// Kernel 2: per-(b,c) top-256 selection (512-bin histogram threshold)
//           + greedy NMS + per-class top-100 out.
// ---------------------------------------------------------------------------
__global__ __launch_bounds__(256, 4) void k_select(const float* __restrict__ regs,
                                                   const float* __restrict__ clfs,
                                                   const float* __restrict__ ctrs) {
  const int c = blockIdx.x, b = blockIdx.y;
  const int tid = threadIdx.x;
  const int lane = tid & 31, wid = tid >> 5;

  __shared__ u32 hist[HBINS];
  __shared__ u64 buf[2048];          // sort buffer (16 KB)
  __shared__ u32 mask[256][8];       // suppression bitmask (8 KB)
  __shared__ float4 bbx[256];        // y1,x1,y2,x2
  __shared__ float bar[256], bsc[256];
  __shared__ u32 chs[257];
  __shared__ u32 validw[8], keepw[8];
  __shared__ int s_tb, s_V;
  __shared__ int warpcnt[8];

  float* ocs = g_cls_s + ((size_t)b * NCLS + c) * 100;
  float* ocb = g_cls_b + ((size_t)b * NCLS + c) * 400;

  const u16* colkeys = g_keys + (size_t)(b * NCLS + c) * NN;
  const uint4* gk4 = (const uint4*)colkeys;   // 8 keys per load
  const u32* gk2 = (const u32*)colkeys;       // 2 keys per load

  // ---- Phase A: 512-bin histogram straight from global (L2-hot) ----
  hist[tid] = 0u; hist[tid + 256] = 0u;
  if (tid == 0) { s_tb = 0; s_V = 0; }
  __syncthreads();

  for (int i = tid; i < NN / 8; i += 256) {
    uint4 w = gk4[i];
    u32 h;
    h = w.x & 0xFFFFu; if (h) atomicAdd(&hist[(h >> 1) - BIN_BASE], 1u);
    h = w.x >> 16;     if (h) atomicAdd(&hist[(h >> 1) - BIN_BASE], 1u);
    h = w.y & 0xFFFFu; if (h) atomicAdd(&hist[(h >> 1) - BIN_BASE], 1u);
    h = w.y >> 16;     if (h) atomicAdd(&hist[(h >> 1) - BIN_BASE], 1u);
    h = w.z & 0xFFFFu; if (h) atomicAdd(&hist[(h >> 1) - BIN_BASE], 1u);
    h = w.z >> 16;     if (h) atomicAdd(&hist[(h >> 1) - BIN_BASE], 1u);
    h = w.w & 0xFFFFu; if (h) atomicAdd(&hist[(h >> 1) - BIN_BASE], 1u);
    h = w.w >> 16;     if (h) atomicAdd(&hist[(h >> 1) - BIN_BASE], 1u);
  }
  __syncthreads();

  // ---- Suffix scan: find largest bin tb with count(bin >= tb) >= target ----
  u32 h0 = hist[2 * tid], h1 = hist[2 * tid + 1];
  chs[tid] = h0 + h1;
  __syncthreads();
  if (tid == 0) {
    u32 run = 0;
    for (int i = 255; i >= 0; i--) { u32 t = chs[i]; chs[i] = run; run += t; }
    chs[256] = run;
  }
  __syncthreads();
  const u32 total = chs[256];
  const u32 target = total < 256u ? total : 256u;

  if (target == 0) {
    for (int i = tid; i < 100; i += 256) ocs[i] = 0.f;
    for (int i = tid; i < 400; i += 256) ocb[i] = 0.f;
    return;
  }
  {
    u32 running = chs[tid];                 // suffix for bins > 2tid+1
    if (running + h1 >= target && running < target) s_tb = 2 * tid + 1;
    u32 r2 = running + h1;                  // suffix for bins > 2tid
    if (r2 + h0 >= target && r2 < target) s_tb = 2 * tid;
  }
  __syncthreads();
  const u32 T2 = (u32)(2 * (s_tb + BIN_BASE));   // select key16 >= T2

  // ---- Collect candidates; recompute exact 32-bit score = fmul(clf, ctr) ----
  const float* clfb = clfs + (size_t)b * NN * NCLS + c;
  const float* ctrb = ctrs + (size_t)b * NN;
  for (int j = tid; j < NN / 2; j += 256) {
    u32 w = gk2[j];
    u32 klo = w & 0xFFFFu, khi = w >> 16;
    if (klo >= T2) {
      int n = 2 * j;
      u32 sb = __float_as_uint(__fmul_rn(clfb[(size_t)n * NCLS], ctrb[n]));
      int p = atomicAdd(&s_V, 1);
      if (p < 2048) buf[p] = ((u64)sb << 32) | (u64)(0xFFFFFFFFu - (u32)n);
    }
    if (khi >= T2) {
      int n = 2 * j + 1;
      u32 sb = __float_as_uint(__fmul_rn(clfb[(size_t)n * NCLS], ctrb[n]));
      int p = atomicAdd(&s_V, 1);
      if (p < 2048) buf[p] = ((u64)sb << 32) | (u64)(0xFFFFFFFFu - (u32)n);
    }
  }
  __syncthreads();
  int V = s_V; if (V > 2048) V = 2048;
  const int M = (V <= 512) ? 512 : (V <= 1024 ? 1024 : 2048);
  for (int i = V + tid; i < M; i += 256) buf[i] = 0ull;
  __syncthreads();

  // Bitonic sort descending on 64-bit keys (stable: low bits = ~index)
  for (int k = 2; k <= M; k <<= 1) {
    for (int j = k >> 1; j > 0; j >>= 1) {
      for (int i = tid; i < M; i += 256) {
        int l = i ^ j;
        if (l > i) {
          u64 a = buf[i], bb2 = buf[l];
          bool up = ((i & k) == 0);
          if (up ? (a < bb2) : (a > bb2)) { buf[i] = bb2; buf[l] = a; }
        }
      }
      __syncthreads();
    }
  }

  // ---- Extract 256 candidates, decode boxes ----
  u64 key = buf[tid];
  float sc = __uint_as_float((u32)(key >> 32));
  bool valid = sc > CONF_T;
  bsc[tid] = sc;
  float y1 = 0.f, x1 = 0.f, y2 = 0.f, x2 = 0.f;
  if (valid) {
    int n = (int)(0xFFFFFFFFu - (u32)key);
    int off, g, lvl;
    if (n < 16384)      { lvl = 0; off = 0;     g = 7; }
    else if (n < 20480) { lvl = 1; off = 16384; g = 6; }
    else if (n < 21504) { lvl = 2; off = 20480; g = 5; }
    else if (n < 21760) { lvl = 3; off = 21504; g = 4; }
    else                { lvl = 4; off = 21760; g = 3; }
    int m = n - off;
    float gx = (float)(m >> g);              // meshgrid 'xy': x is the major axis
    float gy = (float)(m & ((1 << g) - 1));
    float sv = (float)(8 << lvl);
    float4 r = ((const float4*)regs)[(size_t)b * NN + n];
    y1 = __fmul_rn(gy - r.z, sv);
    x1 = __fmul_rn(gx - r.x, sv);
    y2 = __fmul_rn(gy + r.w, sv);
    x2 = __fmul_rn(gx + r.y, sv);
  }
  bbx[tid] = make_float4(y1, x1, y2, x2);
  bar[tid] = __fmul_rn(y2 - y1, x2 - x1);
  u32 vb = __ballot_sync(0xFFFFFFFFu, valid);
  if (lane == 0) validw[wid] = vb;
  __syncthreads();

  // ---- Suppression bitmask (j > i, iou > 0.5; exact IEEE divide) ----
  {
    const int i = tid;
    const float iy1 = y1, ix1 = x1, iy2 = y2, ix2 = x2, ia = bar[i];
#pragma unroll
    for (int w = 0; w < 8; w++) {
      u32 bits = 0;
      if (w * 32 + 31 > i) {
        for (int jj = 0; jj < 32; jj++) {
          int j = w * 32 + jj;
          if (j > i) {
            float4 jb = bbx[j];
            float ih = fminf(iy2, jb.z) - fmaxf(iy1, jb.x);
            float iw = fminf(ix2, jb.w) - fmaxf(ix1, jb.y);
            ih = fmaxf(ih, 0.f); iw = fmaxf(iw, 0.f);
            float inter = __fmul_rn(ih, iw);
            float uni = ia + bar[j] - inter;
            float iou = inter / fmaxf(uni, 1e-8f);
            if (iou > IOU_T) bits |= (1u << jj);
          }
        }
      }
      mask[i][w] = bits;
    }
  }
  __syncthreads();

  // ---- Greedy scan (single thread, branchless, prefetch-friendly) ----
  if (tid == 0) {
    u32 kw[8];
#pragma unroll
    for (int w = 0; w < 8; w++) kw[w] = validw[w];
    for (int i = 0; i < 256; i++) {
      // Unconditional row load: no kw-dependent branch gating the LDS
      const uint4* mr = (const uint4*)&mask[i][0];
      uint4 m0 = mr[0], m1 = mr[1];
      u32 bit = (kw[i >> 5] >> (i & 31)) & 1u;
      u32 sel = (u32)(-(int)bit);
      kw[0] &= ~(m0.x & sel); kw[1] &= ~(m0.y & sel);
      kw[2] &= ~(m0.z & sel); kw[3] &= ~(m0.w & sel);
      kw[4] &= ~(m1.x & sel); kw[5] &= ~(m1.y & sel);
      kw[6] &= ~(m1.z & sel); kw[7] &= ~(m1.w & sel);
    }
#pragma unroll
    for (int w = 0; w < 8; w++) keepw[w] = kw[w];
  }
  __syncthreads();

  // ---- Compact survivors (score-descending) into per-class top-100 ----
  bool kept = (keepw[wid] >> lane) & 1u;
  u32 kb = __ballot_sync(0xFFFFFFFFu, kept);
  if (lane == 0) warpcnt[wid] = __popc(kb);
  __syncthreads();
  int base = 0;
  for (int w = 0; w < wid; w++) base += warpcnt[w];
  int rank = base + __popc(kb & ((1u << lane) - 1u));

  for (int i = tid; i < 100; i += 256) ocs[i] = 0.f;
  for (int i = tid; i < 400; i += 256) ocb[i] = 0.f;
  __syncthreads();
  if (kept && rank < 100) {
    ocs[rank] = bsc[tid];
    float4 bb = bbx[tid];
    ocb[rank * 4 + 0] = bb.x;
    ocb[rank * 4 + 1] = bb.y;
    ocb[rank * 4 + 2] = bb.z;
    ocb[rank * 4 + 3] = bb.w;
  }
}

// ---------------------------------------------------------------------------
// Kernel 3: per-batch stable top-100 of 8000 via threshold search + small sort
// ---------------------------------------------------------------------------
__global__ __launch_bounds__(256) void k_final(float* __restrict__ out) {
  int b = blockIdx.x, tid = threadIdx.x;
  const int lane = tid & 31;
  __shared__ __align__(16) u32 skeys[4000];   // 8000 u16 keys
  __shared__ u64 fbuf[1024];
  __shared__ int s_cnt, s_V;
  const float* cs = g_cls_s + (size_t)b * 8000;

  if (tid == 0) { s_cnt = 0; s_V = 0; }
  const float2* cs2 = (const float2*)cs;
  int cl = 0;
  for (int i = tid; i < 4000; i += 256) {
    float2 v = cs2[i];
    u32 k0 = v.x > 0.f ? (__float_as_uint(v.x) >> 16) : 0u;
    u32 k1 = v.y > 0.f ? (__float_as_uint(v.y) >> 16) : 0u;
    skeys[i] = k0 | (k1 << 16);
    cl += (k0 != 0u) + (k1 != 0u);
  }
  __syncthreads();
  for (int o = 16; o; o >>= 1) cl += __shfl_down_sync(0xFFFFFFFFu, cl, o);
  if (lane == 0 && cl) atomicAdd(&s_cnt, cl);
  __syncthreads();
  const int total = s_cnt;
  const int target = total < 100 ? total : 100;

  u32 T2 = 0;
  if (target > 0) {
    const uint4* sa4 = (const uint4*)skeys;
    int lo = BS_LO, hi = BS_HI;   // kept scores are 0 or in (CONF, 1)
    while (hi - lo > 1) {
      int mid = (lo + hi) >> 1;
      u32 T = (u32)(2 * mid);
      __syncthreads();
      if (tid == 0) s_cnt = 0;
      __syncthreads();
      int cc = 0;
      for (int i = tid; i < 1000; i += 256) {
        uint4 w = sa4[i];
        cc += ((w.x & 0xFFFFu) >= T) + ((w.x >> 16) >= T)
            + ((w.y & 0xFFFFu) >= T) + ((w.y >> 16) >= T)
            + ((w.z & 0xFFFFu) >= T) + ((w.z >> 16) >= T)
            + ((w.w & 0xFFFFu) >= T) + ((w.w >> 16) >= T);
      }
      for (int o = 16; o; o >>= 1) cc += __shfl_down_sync(0xFFFFFFFFu, cc, o);
      if (lane == 0 && cc) atomicAdd(&s_cnt, cc);
      __syncthreads();
      if (s_cnt >= target) lo = mid; else hi = mid;
    }
    T2 = (u32)(2 * lo);

    for (int j = tid; j < 4000; j += 256) {
      u32 w = skeys[j];
      u32 klo = w & 0xFFFFu, khi = w >> 16;
      if (klo >= T2) {
        int n = 2 * j;
        int p = atomicAdd(&s_V, 1);
        if (p < 1024)
          fbuf[p] = ((u64)__float_as_uint(cs[n]) << 32) | (u64)(0xFFFFFFFFu - (u32)n);
      }
      if (khi >= T2) {
        int n = 2 * j + 1;
        int p = atomicAdd(&s_V, 1);
        if (p < 1024)
          fbuf[p] = ((u64)__float_as_uint(cs[n]) << 32) | (u64)(0xFFFFFFFFu - (u32)n);
      }
    }
  }
  // If fewer than 100 positives, fill with lowest-index zero-score slots
  // (stable tie behavior: zeros in [0,256) suffice since >=156 are zero there).
  if (total < 100) {
    int i = tid;  // 256 threads cover flat indices [0,256)
    if (cs[i] == 0.f) {
      int p = atomicAdd(&s_V, 1);
      if (p < 1024) fbuf[p] = (u64)(0xFFFFFFFFu - (u32)i);
    }
  }
  __syncthreads();
  int V = s_V; if (V > 1024) V = 1024;
  const int M = (V <= 128) ? 128 : (V <= 256 ? 256 : (V <= 512 ? 512 : 1024));
  for (int i = V + tid; i < M; i += 256) fbuf[i] = 0ull;
  __syncthreads();

  for (int k = 2; k <= M; k <<= 1) {
    for (int j = k >> 1; j > 0; j >>= 1) {
      for (int i = tid; i < M; i += 256) {
        int l = i ^ j;
        if (l > i) {
          u64 a = fbuf[i], b2 = fbuf[l];
          bool up = ((i & k) == 0);
          if (up ? (a < b2) : (a > b2)) { fbuf[i] = b2; fbuf[l] = a; }
        }
      }
      __syncthreads();
    }
  }

  if (tid < 100) {
    u64 key = fbuf[tid];
    float s = __uint_as_float((u32)(key >> 32));
    int flat = (int)(0xFFFFFFFFu - (u32)key);
    if (flat < 0 || flat >= 8000) { flat = 0; s = 0.f; }  // guard (padding keys)
    float mlt = (s > 0.f) ? 1.f : 0.f;
    const float* bx = g_cls_b + ((size_t)b * 8000 + flat) * 4;
    out[(b * 100 + tid) * 4 + 0] = bx[0] * mlt;
    out[(b * 100 + tid) * 4 + 1] = bx[1] * mlt;
    out[(b * 100 + tid) * 4 + 2] = bx[2] * mlt;
    out[(b * 100 + tid) * 4 + 3] = bx[3] * mlt;
    out[6400 + b * 100 + tid] = (float)(flat / 100);
    out[8000 + b * 100 + tid] = s;
  }
}

// ---------------------------------------------------------------------------
extern "C" void kernel_launch(void* const* d_in, const int* in_sizes, int n_in,
                              void* d_out, int out_size) {
  const float* regs = (const float*)d_in[0];
  const float* ctrs = (const float*)d_in[1];
  const float* clfs = (const float*)d_in[2];
  for (int i = 0; i < n_in; i++) {
    if (in_sizes[i] == BBATCH * NN * 4) regs = (const float*)d_in[i];
    else if (in_sizes[i] == BBATCH * NN) ctrs = (const float*)d_in[i];
    else if (in_sizes[i] == BBATCH * NN * NCLS) clfs = (const float*)d_in[i];
  }
  float* out = (float*)d_out;

  dim3 gT(NN / 32, BBATCH);
  k_transpose<<<gT, 256>>>(clfs, ctrs);

  dim3 gS(NCLS, BBATCH);
  k_select<<<gS, 256>>>(regs, clfs, ctrs);

  k_final<<<BBATCH, 256>>>(out);
}

// round 13
// speedup vs baseline: 1.2570x; 1.1204x over previous
#include <cuda_runtime.h>
#include <stdint.h>

#define NN 21824
#define BBATCH 16
#define NCLS 80
#define CONF_T 0.05f
#define IOU_T 0.5f

typedef unsigned short u16;
typedef unsigned int u32;
typedef unsigned long long u64;

// key16 range for scores in (CONF, 2): [0x3D4C, 0x4000) -> bins (key>>1)-7846 in [0,346)
#define BIN_BASE 7846
#define HBINS 512

// k_final binary-search bounds
#define BS_LO 7846
#define BS_HI 8192

// Scratch (static device globals; no runtime allocation)
__device__ __align__(16) u16 g_keys[(size_t)BBATCH * NCLS * NN];  // 16-bit score keys [b][c][n]
__device__ float g_cls_s[BBATCH * NCLS * 100];          // per-class top-100 scores
__device__ float g_cls_b[BBATCH * NCLS * 100 * 4];      // per-class top-100 boxes

// ---------------------------------------------------------------------------
// Kernel 1: fused score compute + transpose -> 16-bit keys.
// key16[b][c][n] = (clf*ctr > CONF) ? bits(clf*ctr)>>16 : 0
// ---------------------------------------------------------------------------
__global__ __launch_bounds__(256) void k_transpose(const float* __restrict__ clfs,
                                                   const float* __restrict__ ctrs) {
  int b = blockIdx.y;
  int n0 = blockIdx.x * 32;          // NN = 682*32 exactly
  __shared__ float tile[80][33];
  __shared__ float ctr[32];
  int tid = threadIdx.x;
  if (tid < 32) ctr[tid] = ctrs[b * NN + n0 + tid];
  const float4* src = (const float4*)(clfs + ((size_t)b * NN + n0) * NCLS);
  for (int k4 = tid; k4 < 640; k4 += 256) {   // 32*80/4
    float4 v = src[k4];
    int x = k4 / 20, c = (k4 % 20) * 4;       // e = 4*k4; c = e%80 (no wrap), x = e/80
    tile[c][x] = v.x;
    tile[c + 1][x] = v.y;
    tile[c + 2][x] = v.z;
    tile[c + 3][x] = v.w;
  }
  __syncthreads();
  // 80 classes x 16 u32 (32 u16 keys) per block
  for (int k = tid; k < 1280; k += 256) {
    int c = k >> 4, x = (k & 15) * 2;
    float s0 = __fmul_rn(tile[c][x], ctr[x]);
    float s1 = __fmul_rn(tile[c][x + 1], ctr[x + 1]);
    u32 k0 = s0 > CONF_T ? (__float_as_uint(s0) >> 16) : 0u;
    u32 k1 = s1 > CONF_T ? (__float_as_uint(s1) >> 16) : 0u;
    u32* dst = (u32*)(g_keys + ((size_t)b * NCLS + c) * NN + n0);
    dst[k & 15] = k0 | (k1 << 16);
  }
}

// ---------------------------------------------------------------------------
// Kernel 2: per-(b,c) top-256 selection (512-bin histogram threshold)
//           + greedy NMS + per-class top-100 out.
// ---------------------------------------------------------------------------
__global__ __launch_bounds__(256, 4) void k_select(const float* __restrict__ regs,
                                                   const float* __restrict__ clfs,
                                                   const float* __restrict__ ctrs) {
  const int c = blockIdx.x, b = blockIdx.y;
  const int tid = threadIdx.x;
  const int lane = tid & 31, wid = tid >> 5;

  __shared__ u32 hist[HBINS];
  __shared__ u64 buf[2048];          // sort buffer (16 KB)
  __shared__ u32 mask[256][8];       // suppression bitmask (8 KB)
  __shared__ float4 bbx[256];        // y1,x1,y2,x2
  __shared__ float bar[256], bsc[256];
  __shared__ u32 chs[257];
  __shared__ u32 validw[8], keepw[8];
  __shared__ int s_tb, s_V;
  __shared__ int warpcnt[8];

  float* ocs = g_cls_s + ((size_t)b * NCLS + c) * 100;
  float* ocb = g_cls_b + ((size_t)b * NCLS + c) * 400;

  const u16* colkeys = g_keys + (size_t)(b * NCLS + c) * NN;
  const uint4* gk4 = (const uint4*)colkeys;   // 8 keys per load
  const u32* gk2 = (const u32*)colkeys;       // 2 keys per load

  // ---- Phase A: 512-bin histogram straight from global (L2-hot) ----
  hist[tid] = 0u; hist[tid + 256] = 0u;
  if (tid == 0) { s_tb = 0; s_V = 0; }
  __syncthreads();

  for (int i = tid; i < NN / 8; i += 256) {
    uint4 w = gk4[i];
    u32 h;
    h = w.x & 0xFFFFu; if (h) atomicAdd(&hist[(h >> 1) - BIN_BASE], 1u);
    h = w.x >> 16;     if (h) atomicAdd(&hist[(h >> 1) - BIN_BASE], 1u);
    h = w.y & 0xFFFFu; if (h) atomicAdd(&hist[(h >> 1) - BIN_BASE], 1u);
    h = w.y >> 16;     if (h) atomicAdd(&hist[(h >> 1) - BIN_BASE], 1u);
    h = w.z & 0xFFFFu; if (h) atomicAdd(&hist[(h >> 1) - BIN_BASE], 1u);
    h = w.z >> 16;     if (h) atomicAdd(&hist[(h >> 1) - BIN_BASE], 1u);
    h = w.w & 0xFFFFu; if (h) atomicAdd(&hist[(h >> 1) - BIN_BASE], 1u);
    h = w.w >> 16;     if (h) atomicAdd(&hist[(h >> 1) - BIN_BASE], 1u);
  }
  __syncthreads();

  // ---- Suffix scan: find largest bin tb with count(bin >= tb) >= target ----
  u32 h0 = hist[2 * tid], h1 = hist[2 * tid + 1];
  chs[tid] = h0 + h1;
  __syncthreads();
  if (tid == 0) {
    u32 run = 0;
    for (int i = 255; i >= 0; i--) { u32 t = chs[i]; chs[i] = run; run += t; }
    chs[256] = run;
  }
  __syncthreads();
  const u32 total = chs[256];
  const u32 target = total < 256u ? total : 256u;

  if (target == 0) {
    for (int i = tid; i < 100; i += 256) ocs[i] = 0.f;
    for (int i = tid; i < 400; i += 256) ocb[i] = 0.f;
    return;
  }
  {
    u32 running = chs[tid];                 // suffix for bins > 2tid+1
    if (running + h1 >= target && running < target) s_tb = 2 * tid + 1;
    u32 r2 = running + h1;                  // suffix for bins > 2tid
    if (r2 + h0 >= target && r2 < target) s_tb = 2 * tid;
  }
  __syncthreads();
  const u32 T2 = (u32)(2 * (s_tb + BIN_BASE));   // select key16 >= T2

  // ---- Collect candidates; recompute exact 32-bit score = fmul(clf, ctr) ----
  const float* clfb = clfs + (size_t)b * NN * NCLS + c;
  const float* ctrb = ctrs + (size_t)b * NN;
  for (int j = tid; j < NN / 2; j += 256) {
    u32 w = gk2[j];
    u32 klo = w & 0xFFFFu, khi = w >> 16;
    if (klo >= T2) {
      int n = 2 * j;
      u32 sb = __float_as_uint(__fmul_rn(clfb[(size_t)n * NCLS], ctrb[n]));
      int p = atomicAdd(&s_V, 1);
      if (p < 2048) buf[p] = ((u64)sb << 32) | (u64)(0xFFFFFFFFu - (u32)n);
    }
    if (khi >= T2) {
      int n = 2 * j + 1;
      u32 sb = __float_as_uint(__fmul_rn(clfb[(size_t)n * NCLS], ctrb[n]));
      int p = atomicAdd(&s_V, 1);
      if (p < 2048) buf[p] = ((u64)sb << 32) | (u64)(0xFFFFFFFFu - (u32)n);
    }
  }
  __syncthreads();
  int V = s_V; if (V > 2048) V = 2048;
  const int M = (V <= 512) ? 512 : (V <= 1024 ? 1024 : 2048);
  for (int i = V + tid; i < M; i += 256) buf[i] = 0ull;
  __syncthreads();

  // Bitonic sort descending on 64-bit keys (stable: low bits = ~index)
  for (int k = 2; k <= M; k <<= 1) {
    for (int j = k >> 1; j > 0; j >>= 1) {
      for (int i = tid; i < M; i += 256) {
        int l = i ^ j;
        if (l > i) {
          u64 a = buf[i], bb2 = buf[l];
          bool up = ((i & k) == 0);
          if (up ? (a < bb2) : (a > bb2)) { buf[i] = bb2; buf[l] = a; }
        }
      }
      __syncthreads();
    }
  }

  // ---- Extract 256 candidates, decode boxes ----
  u64 key = buf[tid];
  float sc = __uint_as_float((u32)(key >> 32));
  bool valid = sc > CONF_T;
  bsc[tid] = sc;
  float y1 = 0.f, x1 = 0.f, y2 = 0.f, x2 = 0.f;
  if (valid) {
    int n = (int)(0xFFFFFFFFu - (u32)key);
    int off, g, lvl;
    if (n < 16384)      { lvl = 0; off = 0;     g = 7; }
    else if (n < 20480) { lvl = 1; off = 16384; g = 6; }
    else if (n < 21504) { lvl = 2; off = 20480; g = 5; }
    else if (n < 21760) { lvl = 3; off = 21504; g = 4; }
    else                { lvl = 4; off = 21760; g = 3; }
    int m = n - off;
    float gx = (float)(m >> g);              // meshgrid 'xy': x is the major axis
    float gy = (float)(m & ((1 << g) - 1));
    float sv = (float)(8 << lvl);
    float4 r = ((const float4*)regs)[(size_t)b * NN + n];
    y1 = __fmul_rn(gy - r.z, sv);
    x1 = __fmul_rn(gx - r.x, sv);
    y2 = __fmul_rn(gy + r.w, sv);
    x2 = __fmul_rn(gx + r.y, sv);
  }
  bbx[tid] = make_float4(y1, x1, y2, x2);
  bar[tid] = __fmul_rn(y2 - y1, x2 - x1);
  u32 vb = __ballot_sync(0xFFFFFFFFu, valid);
  if (lane == 0) validw[wid] = vb;
  __syncthreads();

  // ---- Suppression bitmask (j > i, iou > 0.5) ----
  // Divide-free predicate, bit-exact to RN(inter/max(uni,1e-8)) > 0.5:
  //   t = 0.5f*b is exact; "RN(a/b) > 0.5" <=> real a/b > 0.5+2^-25
  //   <=> a > t*(1+2^-24); since t*2^-24 in [ulp(t)/2, ulp(t)), a float a
  //   exceeds that iff a > t.
  {
    const int i = tid;
    const float iy1 = y1, ix1 = x1, iy2 = y2, ix2 = x2, ia = bar[i];
#pragma unroll
    for (int w = 0; w < 8; w++) {
      u32 bits = 0;
      if (w * 32 + 31 > i) {
        for (int jj = 0; jj < 32; jj++) {
          int j = w * 32 + jj;
          if (j > i) {
            float4 jb = bbx[j];
            float ih = fminf(iy2, jb.z) - fmaxf(iy1, jb.x);
            float iw = fminf(ix2, jb.w) - fmaxf(ix1, jb.y);
            ih = fmaxf(ih, 0.f); iw = fmaxf(iw, 0.f);
            float inter = __fmul_rn(ih, iw);
            float uni = ia + bar[j] - inter;
            float halfu = __fmul_rn(0.5f, fmaxf(uni, 1e-8f));
            if (inter > halfu) bits |= (1u << jj);
          }
        }
      }
      mask[i][w] = bits;
    }
  }
  __syncthreads();

  // ---- Greedy scan (single thread, branchless, prefetch-friendly) ----
  if (tid == 0) {
    u32 kw[8];
#pragma unroll
    for (int w = 0; w < 8; w++) kw[w] = validw[w];
    for (int i = 0; i < 256; i++) {
      const uint4* mr = (const uint4*)&mask[i][0];
      uint4 m0 = mr[0], m1 = mr[1];
      u32 bit = (kw[i >> 5] >> (i & 31)) & 1u;
      u32 sel = (u32)(-(int)bit);
      kw[0] &= ~(m0.x & sel); kw[1] &= ~(m0.y & sel);
      kw[2] &= ~(m0.z & sel); kw[3] &= ~(m0.w & sel);
      kw[4] &= ~(m1.x & sel); kw[5] &= ~(m1.y & sel);
      kw[6] &= ~(m1.z & sel); kw[7] &= ~(m1.w & sel);
    }
#pragma unroll
    for (int w = 0; w < 8; w++) keepw[w] = kw[w];
  }
  __syncthreads();

  // ---- Compact survivors (score-descending) into per-class top-100 ----
  bool kept = (keepw[wid] >> lane) & 1u;
  u32 kb = __ballot_sync(0xFFFFFFFFu, kept);
  if (lane == 0) warpcnt[wid] = __popc(kb);
  __syncthreads();
  int base = 0;
  for (int w = 0; w < wid; w++) base += warpcnt[w];
  int rank = base + __popc(kb & ((1u << lane) - 1u));

  for (int i = tid; i < 100; i += 256) ocs[i] = 0.f;
  for (int i = tid; i < 400; i += 256) ocb[i] = 0.f;
  __syncthreads();
  if (kept && rank < 100) {
    ocs[rank] = bsc[tid];
    float4 bb = bbx[tid];
    ocb[rank * 4 + 0] = bb.x;
    ocb[rank * 4 + 1] = bb.y;
    ocb[rank * 4 + 2] = bb.z;
    ocb[rank * 4 + 3] = bb.w;
  }
}

// ---------------------------------------------------------------------------
// Kernel 3: per-batch stable top-100 of 8000 via threshold search + small sort
// ---------------------------------------------------------------------------
__global__ __launch_bounds__(256) void k_final(float* __restrict__ out) {
  int b = blockIdx.x, tid = threadIdx.x;
  const int lane = tid & 31;
  __shared__ __align__(16) u32 skeys[4000];   // 8000 u16 keys
  __shared__ u64 fbuf[1024];
  __shared__ int s_cnt, s_V;
  const float* cs = g_cls_s + (size_t)b * 8000;

  if (tid == 0) { s_cnt = 0; s_V = 0; }
  const float2* cs2 = (const float2*)cs;
  int cl = 0;
  for (int i = tid; i < 4000; i += 256) {
    float2 v = cs2[i];
    u32 k0 = v.x > 0.f ? (__float_as_uint(v.x) >> 16) : 0u;
    u32 k1 = v.y > 0.f ? (__float_as_uint(v.y) >> 16) : 0u;
    skeys[i] = k0 | (k1 << 16);
    cl += (k0 != 0u) + (k1 != 0u);
  }
  __syncthreads();
  for (int o = 16; o; o >>= 1) cl += __shfl_down_sync(0xFFFFFFFFu, cl, o);
  if (lane == 0 && cl) atomicAdd(&s_cnt, cl);
  __syncthreads();
  const int total = s_cnt;
  const int target = total < 100 ? total : 100;

  u32 T2 = 0;
  if (target > 0) {
    const uint4* sa4 = (const uint4*)skeys;
    int lo = BS_LO, hi = BS_HI;   // kept scores are 0 or in (CONF, 1)
    while (hi - lo > 1) {
      int mid = (lo + hi) >> 1;
      u32 T = (u32)(2 * mid);
      __syncthreads();
      if (tid == 0) s_cnt = 0;
      __syncthreads();
      int cc = 0;
      for (int i = tid; i < 1000; i += 256) {
        uint4 w = sa4[i];
        cc += ((w.x & 0xFFFFu) >= T) + ((w.x >> 16) >= T)
            + ((w.y & 0xFFFFu) >= T) + ((w.y >> 16) >= T)
            + ((w.z & 0xFFFFu) >= T) + ((w.z >> 16) >= T)
            + ((w.w & 0xFFFFu) >= T) + ((w.w >> 16) >= T);
      }
      for (int o = 16; o; o >>= 1) cc += __shfl_down_sync(0xFFFFFFFFu, cc, o);
      if (lane == 0 && cc) atomicAdd(&s_cnt, cc);
      __syncthreads();
      if (s_cnt >= target) lo = mid; else hi = mid;
    }
    T2 = (u32)(2 * lo);

    for (int j = tid; j < 4000; j += 256) {
      u32 w = skeys[j];
      u32 klo = w & 0xFFFFu, khi = w >> 16;
      if (klo >= T2) {
        int n = 2 * j;
        int p = atomicAdd(&s_V, 1);
        if (p < 1024)
          fbuf[p] = ((u64)__float_as_uint(cs[n]) << 32) | (u64)(0xFFFFFFFFu - (u32)n);
      }
      if (khi >= T2) {
        int n = 2 * j + 1;
        int p = atomicAdd(&s_V, 1);
        if (p < 1024)
          fbuf[p] = ((u64)__float_as_uint(cs[n]) << 32) | (u64)(0xFFFFFFFFu - (u32)n);
      }
    }
  }
  // If fewer than 100 positives, fill with lowest-index zero-score slots
  // (stable tie behavior: zeros in [0,256) suffice since >=156 are zero there).
  if (total < 100) {
    int i = tid;  // 256 threads cover flat indices [0,256)
    if (cs[i] == 0.f) {
      int p = atomicAdd(&s_V, 1);
      if (p < 1024) fbuf[p] = (u64)(0xFFFFFFFFu - (u32)i);
    }
  }
  __syncthreads();
  int V = s_V; if (V > 1024) V = 1024;
  const int M = (V <= 128) ? 128 : (V <= 256 ? 256 : (V <= 512 ? 512 : 1024));
  for (int i = V + tid; i < M; i += 256) fbuf[i] = 0ull;
  __syncthreads();

  for (int k = 2; k <= M; k <<= 1) {
    for (int j = k >> 1; j > 0; j >>= 1) {
      for (int i = tid; i < M; i += 256) {
        int l = i ^ j;
        if (l > i) {
          u64 a = fbuf[i], b2 = fbuf[l];
          bool up = ((i & k) == 0);
          if (up ? (a < b2) : (a > b2)) { fbuf[i] = b2; fbuf[l] = a; }
        }
      }
      __syncthreads();
    }
  }

  if (tid < 100) {
    u64 key = fbuf[tid];
    float s = __uint_as_float((u32)(key >> 32));
    int flat = (int)(0xFFFFFFFFu - (u32)key);
    if (flat < 0 || flat >= 8000) { flat = 0; s = 0.f; }  // guard (padding keys)
    float mlt = (s > 0.f) ? 1.f : 0.f;
    const float* bx = g_cls_b + ((size_t)b * 8000 + flat) * 4;
    out[(b * 100 + tid) * 4 + 0] = bx[0] * mlt;
    out[(b * 100 + tid) * 4 + 1] = bx[1] * mlt;
    out[(b * 100 + tid) * 4 + 2] = bx[2] * mlt;
    out[(b * 100 + tid) * 4 + 3] = bx[3] * mlt;
    out[6400 + b * 100 + tid] = (float)(flat / 100);
    out[8000 + b * 100 + tid] = s;
  }
}

// ---------------------------------------------------------------------------
extern "C" void kernel_launch(void* const* d_in, const int* in_sizes, int n_in,
                              void* d_out, int out_size) {
  const float* regs = (const float*)d_in[0];
  const float* ctrs = (const float*)d_in[1];
  const float* clfs = (const float*)d_in[2];
  for (int i = 0; i < n_in; i++) {
    if (in_sizes[i] == BBATCH * NN * 4) regs = (const float*)d_in[i];
    else if (in_sizes[i] == BBATCH * NN) ctrs = (const float*)d_in[i];
    else if (in_sizes[i] == BBATCH * NN * NCLS) clfs = (const float*)d_in[i];
  }
  float* out = (float*)d_out;

  dim3 gT(NN / 32, BBATCH);
  k_transpose<<<gT, 256>>>(clfs, ctrs);

  dim3 gS(NCLS, BBATCH);
  k_select<<<gS, 256>>>(regs, clfs, ctrs);

  k_final<<<BBATCH, 256>>>(out);
}

// round 14
// speedup vs baseline: 1.6922x; 1.3462x over previous
#include <cuda_runtime.h>
#include <stdint.h>

#define NN 21824
#define BBATCH 16
#define NCLS 80
#define CONF_T 0.05f
#define IOU_T 0.5f

typedef unsigned short u16;
typedef unsigned int u32;
typedef unsigned long long u64;

// key16 range for scores in (CONF, 2): [0x3D4C, 0x4000) -> bins (key>>1)-7846 in [0,346)
#define BIN_BASE 7846
#define HBINS 512

// k_final binary-search bounds
#define BS_LO 7846
#define BS_HI 8192

// Scratch (static device globals; no runtime allocation)
__device__ __align__(16) u16 g_keys[(size_t)BBATCH * NCLS * NN];  // 16-bit score keys [b][c][n]
__device__ float g_cls_s[BBATCH * NCLS * 100];          // per-class top-100 scores
__device__ float g_cls_b[BBATCH * NCLS * 100 * 4];      // per-class top-100 boxes

// ---------------------------------------------------------------------------
// Kernel 1: fused score compute + transpose -> 16-bit keys. 64-anchor tiles.
// key16[b][c][n] = (clf*ctr > CONF) ? bits(clf*ctr)>>16 : 0
// ---------------------------------------------------------------------------
__global__ __launch_bounds__(256) void k_transpose(const float* __restrict__ clfs,
                                                   const float* __restrict__ ctrs) {
  int b = blockIdx.y;
  int n0 = blockIdx.x * 64;          // NN = 341*64 exactly
  __shared__ float tile[80][66];
  __shared__ float ctr[64];
  int tid = threadIdx.x;
  if (tid < 64) ctr[tid] = ctrs[b * NN + n0 + tid];
  const float4* src = (const float4*)(clfs + ((size_t)b * NN + n0) * NCLS);
  for (int k4 = tid; k4 < 1280; k4 += 256) {   // 64*80/4
    float4 v = src[k4];
    int x = k4 / 20, c = (k4 % 20) * 4;        // e = 4*k4; c = e%80 (no wrap), x = e/80
    tile[c][x] = v.x;
    tile[c + 1][x] = v.y;
    tile[c + 2][x] = v.z;
    tile[c + 3][x] = v.w;
  }
  __syncthreads();
  // 80 classes x 32 u32 (64 u16 keys) per block -> 128B coalesced runs
  for (int k = tid; k < 2560; k += 256) {
    int c = k >> 5, xi = (k & 31) * 2;
    float s0 = __fmul_rn(tile[c][xi], ctr[xi]);
    float s1 = __fmul_rn(tile[c][xi + 1], ctr[xi + 1]);
    u32 k0 = s0 > CONF_T ? (__float_as_uint(s0) >> 16) : 0u;
    u32 k1 = s1 > CONF_T ? (__float_as_uint(s1) >> 16) : 0u;
    u32* dst = (u32*)(g_keys + ((size_t)b * NCLS + c) * NN + n0);
    dst[k & 31] = k0 | (k1 << 16);
  }
}

// ---------------------------------------------------------------------------
// Kernel 2: per-(b,c) top-256 selection + greedy NMS, 512 threads/block.
// ---------------------------------------------------------------------------
__global__ __launch_bounds__(512, 2) void k_select(const float* __restrict__ regs,
                                                   const float* __restrict__ clfs,
                                                   const float* __restrict__ ctrs) {
  const int c = blockIdx.x, b = blockIdx.y;
  const int tid = threadIdx.x;
  const int lane = tid & 31, wid = tid >> 5;

  __shared__ u32 hist[HBINS];
  __shared__ u64 buf[2048];          // sort buffer / exchange scratch (16 KB)
  __shared__ u32 mask[256][8];       // suppression bitmask (8 KB)
  __shared__ float4 bbx[256];        // y1,x1,y2,x2
  __shared__ float bar[256];
  __shared__ u32 chs[257];
  __shared__ u32 validw[8], keepw[8];
  __shared__ int s_tb, s_V;
  __shared__ int warpcnt[8];

  float* ocs = g_cls_s + ((size_t)b * NCLS + c) * 100;
  float* ocb = g_cls_b + ((size_t)b * NCLS + c) * 400;

  const u16* colkeys = g_keys + (size_t)(b * NCLS + c) * NN;
  const uint4* gk4 = (const uint4*)colkeys;   // 8 keys per load
  const u32* gk2 = (const u32*)colkeys;       // 2 keys per load

  // ---- Phase A: 512-bin histogram straight from global (L2-hot) ----
  hist[tid] = 0u;
  if (tid == 0) { s_tb = 0; s_V = 0; }
  __syncthreads();

  for (int i = tid; i < NN / 8; i += 512) {
    uint4 w = gk4[i];
    u32 h;
    h = w.x & 0xFFFFu; if (h) atomicAdd(&hist[(h >> 1) - BIN_BASE], 1u);
    h = w.x >> 16;     if (h) atomicAdd(&hist[(h >> 1) - BIN_BASE], 1u);
    h = w.y & 0xFFFFu; if (h) atomicAdd(&hist[(h >> 1) - BIN_BASE], 1u);
    h = w.y >> 16;     if (h) atomicAdd(&hist[(h >> 1) - BIN_BASE], 1u);
    h = w.z & 0xFFFFu; if (h) atomicAdd(&hist[(h >> 1) - BIN_BASE], 1u);
    h = w.z >> 16;     if (h) atomicAdd(&hist[(h >> 1) - BIN_BASE], 1u);
    h = w.w & 0xFFFFu; if (h) atomicAdd(&hist[(h >> 1) - BIN_BASE], 1u);
    h = w.w >> 16;     if (h) atomicAdd(&hist[(h >> 1) - BIN_BASE], 1u);
  }
  __syncthreads();

  // ---- Suffix scan: find largest bin tb with count(bin >= tb) >= target ----
  u32 h0 = 0, h1 = 0;
  if (tid < 256) {
    h0 = hist[2 * tid]; h1 = hist[2 * tid + 1];
    chs[tid] = h0 + h1;
  }
  __syncthreads();
  if (tid == 0) {
    u32 run = 0;
    for (int i = 255; i >= 0; i--) { u32 t = chs[i]; chs[i] = run; run += t; }
    chs[256] = run;
  }
  __syncthreads();
  const u32 total = chs[256];
  const u32 target = total < 256u ? total : 256u;

  if (target == 0) {
    for (int i = tid; i < 100; i += 512) ocs[i] = 0.f;
    for (int i = tid; i < 400; i += 512) ocb[i] = 0.f;
    return;
  }
  if (tid < 256) {
    u32 running = chs[tid];                 // suffix for bins > 2tid+1
    if (running + h1 >= target && running < target) s_tb = 2 * tid + 1;
    u32 r2 = running + h1;                  // suffix for bins > 2tid
    if (r2 + h0 >= target && r2 < target) s_tb = 2 * tid;
  }
  __syncthreads();
  const u32 T2 = (u32)(2 * (s_tb + BIN_BASE));   // select key16 >= T2

  // ---- Collect candidates; recompute exact 32-bit score = fmul(clf, ctr) ----
  const float* clfb = clfs + (size_t)b * NN * NCLS + c;
  const float* ctrb = ctrs + (size_t)b * NN;
  for (int j = tid; j < NN / 2; j += 512) {
    u32 w = gk2[j];
    u32 klo = w & 0xFFFFu, khi = w >> 16;
    if (klo >= T2) {
      int n = 2 * j;
      u32 sb = __float_as_uint(__fmul_rn(clfb[(size_t)n * NCLS], ctrb[n]));
      int p = atomicAdd(&s_V, 1);
      if (p < 2048) buf[p] = ((u64)sb << 32) | (u64)(0xFFFFFFFFu - (u32)n);
    }
    if (khi >= T2) {
      int n = 2 * j + 1;
      u32 sb = __float_as_uint(__fmul_rn(clfb[(size_t)n * NCLS], ctrb[n]));
      int p = atomicAdd(&s_V, 1);
      if (p < 2048) buf[p] = ((u64)sb << 32) | (u64)(0xFFFFFFFFu - (u32)n);
    }
  }
  __syncthreads();
  int V = s_V; if (V > 2048) V = 2048;
  const int M = (V <= 512) ? 512 : (V <= 1024 ? 1024 : 2048);
  for (int i = V + tid; i < M; i += 512) buf[i] = 0ull;
  __syncthreads();

  // ---- Bitonic sort descending (keys unique -> result network-independent) ----
  u64 key;
  if (M == 512) {
    // Register-resident: 1 element/thread; shfl for j<32, shared for j>=32.
    u64 v = buf[tid];
    for (int k = 2; k <= 512; k <<= 1) {
      for (int j = k >> 1; j > 0; j >>= 1) {
        u64 pv;
        if (j >= 32) {
          __syncthreads();
          buf[tid] = v;
          __syncthreads();
          pv = buf[tid ^ j];
        } else {
          u32 lo = (u32)v, hi = (u32)(v >> 32);
          lo = __shfl_xor_sync(0xFFFFFFFFu, lo, j);
          hi = __shfl_xor_sync(0xFFFFFFFFu, hi, j);
          pv = ((u64)hi << 32) | lo;
        }
        bool keepMax = (((tid & j) == 0) == ((tid & k) == 0));
        u64 mx = (v >= pv) ? v : pv;
        u64 mn = (v >= pv) ? pv : v;
        v = keepMax ? mx : mn;
      }
    }
    key = v;                      // element at position tid
    __syncthreads();              // buf reads done before any reuse
  } else {
    for (int k = 2; k <= M; k <<= 1) {
      for (int j = k >> 1; j > 0; j >>= 1) {
        for (int i = tid; i < M; i += 512) {
          int l = i ^ j;
          if (l > i) {
            u64 a = buf[i], bb2 = buf[l];
            bool up = ((i & k) == 0);
            if (up ? (a < bb2) : (a > bb2)) { buf[i] = bb2; buf[l] = a; }
          }
        }
        __syncthreads();
      }
    }
    key = (tid < 256) ? buf[tid] : 0ull;
  }

  // ---- Extract 256 candidates, decode boxes (threads 0..255) ----
  float sc = 0.f;
  bool valid = false;
  if (tid < 256) {
    sc = __uint_as_float((u32)(key >> 32));
    valid = sc > CONF_T;
    float y1 = 0.f, x1 = 0.f, y2 = 0.f, x2 = 0.f;
    if (valid) {
      int n = (int)(0xFFFFFFFFu - (u32)key);
      int off, g, lvl;
      if (n < 16384)      { lvl = 0; off = 0;     g = 7; }
      else if (n < 20480) { lvl = 1; off = 16384; g = 6; }
      else if (n < 21504) { lvl = 2; off = 20480; g = 5; }
      else if (n < 21760) { lvl = 3; off = 21504; g = 4; }
      else                { lvl = 4; off = 21760; g = 3; }
      int m = n - off;
      float gx = (float)(m >> g);              // meshgrid 'xy': x is the major axis
      float gy = (float)(m & ((1 << g) - 1));
      float sv = (float)(8 << lvl);
      float4 r = ((const float4*)regs)[(size_t)b * NN + n];
      y1 = __fmul_rn(gy - r.z, sv);
      x1 = __fmul_rn(gx - r.x, sv);
      y2 = __fmul_rn(gy + r.w, sv);
      x2 = __fmul_rn(gx + r.y, sv);
    }
    bbx[tid] = make_float4(y1, x1, y2, x2);
    bar[tid] = __fmul_rn(y2 - y1, x2 - x1);
    u32 vb = __ballot_sync(0xFFFFFFFFu, valid);
    if (lane == 0) validw[wid] = vb;
  }
  __syncthreads();

  // ---- Suppression bitmask: 2 threads per row, 4 words each ----
  // Divide-free predicate, bit-exact to RN(inter/max(uni,1e-8)) > 0.5:
  //   t = 0.5f*b exact; "RN(a/b) > 0.5" <=> a > t*(1+2^-24) <=> (float a) > t.
  {
    const int i = tid & 255;
    const int h4 = (tid >> 8) * 4;        // word group: 0..3 or 4..7
    const float4 ib = bbx[i];
    const float ia = bar[i];
    const int wlo = i >> 5;
#pragma unroll
    for (int w = h4; w < h4 + 4; w++) {
      u32 bits = 0;
      if (w >= wlo) {
        int j = (w == wlo) ? (i + 1) : (w * 32);
        int j1 = w * 32 + 32;
        for (; j < j1; j++) {
          float4 jb = bbx[j];
          float ih = fminf(ib.z, jb.z) - fmaxf(ib.x, jb.x);
          float iw = fminf(ib.w, jb.w) - fmaxf(ib.y, jb.y);
          ih = fmaxf(ih, 0.f); iw = fmaxf(iw, 0.f);
          float inter = __fmul_rn(ih, iw);
          float uni = ia + bar[j] - inter;
          float halfu = __fmul_rn(0.5f, fmaxf(uni, 1e-8f));
          if (inter > halfu) bits |= (1u << (j & 31));
        }
      }
      mask[i][w] = bits;
    }
  }
  __syncthreads();

  // ---- Greedy scan (single thread, branchless) ----
  if (tid == 0) {
    u32 kw[8];
#pragma unroll
    for (int w = 0; w < 8; w++) kw[w] = validw[w];
    for (int i = 0; i < 256; i++) {
      const uint4* mr = (const uint4*)&mask[i][0];
      uint4 m0 = mr[0], m1 = mr[1];
      u32 bit = (kw[i >> 5] >> (i & 31)) & 1u;
      u32 sel = (u32)(-(int)bit);
      kw[0] &= ~(m0.x & sel); kw[1] &= ~(m0.y & sel);
      kw[2] &= ~(m0.z & sel); kw[3] &= ~(m0.w & sel);
      kw[4] &= ~(m1.x & sel); kw[5] &= ~(m1.y & sel);
      kw[6] &= ~(m1.z & sel); kw[7] &= ~(m1.w & sel);
    }
#pragma unroll
    for (int w = 0; w < 8; w++) keepw[w] = kw[w];
  }
  __syncthreads();

  // ---- Compact survivors (score-descending) into per-class top-100 ----
  bool kept = false;
  u32 kb = 0;
  if (tid < 256) {
    kept = (keepw[wid] >> lane) & 1u;
    kb = __ballot_sync(0xFFFFFFFFu, kept);
    if (lane == 0) warpcnt[wid] = __popc(kb);
  }
  for (int i = tid; i < 100; i += 512) ocs[i] = 0.f;
  for (int i = tid; i < 400; i += 512) ocb[i] = 0.f;
  __syncthreads();
  if (tid < 256) {
    int base = 0;
    for (int w = 0; w < wid; w++) base += warpcnt[w];
    int rank = base + __popc(kb & ((1u << lane) - 1u));
    if (kept && rank < 100) {
      ocs[rank] = sc;
      float4 bb = bbx[tid];
      ocb[rank * 4 + 0] = bb.x;
      ocb[rank * 4 + 1] = bb.y;
      ocb[rank * 4 + 2] = bb.z;
      ocb[rank * 4 + 3] = bb.w;
    }
  }
}

// ---------------------------------------------------------------------------
// Kernel 3: per-batch stable top-100 of 8000 via threshold search + small sort
// ---------------------------------------------------------------------------
__global__ __launch_bounds__(256) void k_final(float* __restrict__ out) {
  int b = blockIdx.x, tid = threadIdx.x;
  const int lane = tid & 31;
  __shared__ __align__(16) u32 skeys[4000];   // 8000 u16 keys
  __shared__ u64 fbuf[1024];
  __shared__ int s_cnt, s_V;
  const float* cs = g_cls_s + (size_t)b * 8000;

  if (tid == 0) { s_cnt = 0; s_V = 0; }
  const float2* cs2 = (const float2*)cs;
  int cl = 0;
  for (int i = tid; i < 4000; i += 256) {
    float2 v = cs2[i];
    u32 k0 = v.x > 0.f ? (__float_as_uint(v.x) >> 16) : 0u;
    u32 k1 = v.y > 0.f ? (__float_as_uint(v.y) >> 16) : 0u;
    skeys[i] = k0 | (k1 << 16);
    cl += (k0 != 0u) + (k1 != 0u);
  }
  __syncthreads();
  for (int o = 16; o; o >>= 1) cl += __shfl_down_sync(0xFFFFFFFFu, cl, o);
  if (lane == 0 && cl) atomicAdd(&s_cnt, cl);
  __syncthreads();
  const int total = s_cnt;
  const int target = total < 100 ? total : 100;

  u32 T2 = 0;
  if (target > 0) {
    const uint4* sa4 = (const uint4*)skeys;
    int lo = BS_LO, hi = BS_HI;   // kept scores are 0 or in (CONF, 1)
    while (hi - lo > 1) {
      int mid = (lo + hi) >> 1;
      u32 T = (u32)(2 * mid);
      __syncthreads();
      if (tid == 0) s_cnt = 0;
      __syncthreads();
      int cc = 0;
      for (int i = tid; i < 1000; i += 256) {
        uint4 w = sa4[i];
        cc += ((w.x & 0xFFFFu) >= T) + ((w.x >> 16) >= T)
            + ((w.y & 0xFFFFu) >= T) + ((w.y >> 16) >= T)
            + ((w.z & 0xFFFFu) >= T) + ((w.z >> 16) >= T)
            + ((w.w & 0xFFFFu) >= T) + ((w.w >> 16) >= T);
      }
      for (int o = 16; o; o >>= 1) cc += __shfl_down_sync(0xFFFFFFFFu, cc, o);
      if (lane == 0 && cc) atomicAdd(&s_cnt, cc);
      __syncthreads();
      if (s_cnt >= target) lo = mid; else hi = mid;
    }
    T2 = (u32)(2 * lo);

    for (int j = tid; j < 4000; j += 256) {
      u32 w = skeys[j];
      u32 klo = w & 0xFFFFu, khi = w >> 16;
      if (klo >= T2) {
        int n = 2 * j;
        int p = atomicAdd(&s_V, 1);
        if (p < 1024)
          fbuf[p] = ((u64)__float_as_uint(cs[n]) << 32) | (u64)(0xFFFFFFFFu - (u32)n);
      }
      if (khi >= T2) {
        int n = 2 * j + 1;
        int p = atomicAdd(&s_V, 1);
        if (p < 1024)
          fbuf[p] = ((u64)__float_as_uint(cs[n]) << 32) | (u64)(0xFFFFFFFFu - (u32)n);
      }
    }
  }
  // If fewer than 100 positives, fill with lowest-index zero-score slots
  // (stable tie behavior: zeros in [0,256) suffice since >=156 are zero there).
  if (total < 100) {
    int i = tid;  // 256 threads cover flat indices [0,256)
    if (cs[i] == 0.f) {
      int p = atomicAdd(&s_V, 1);
      if (p < 1024) fbuf[p] = (u64)(0xFFFFFFFFu - (u32)i);
    }
  }
  __syncthreads();
  int V = s_V; if (V > 1024) V = 1024;
  const int M = (V <= 128) ? 128 : (V <= 256 ? 256 : (V <= 512 ? 512 : 1024));
  for (int i = V + tid; i < M; i += 256) fbuf[i] = 0ull;
  __syncthreads();

  for (int k = 2; k <= M; k <<= 1) {
    for (int j = k >> 1; j > 0; j >>= 1) {
      for (int i = tid; i < M; i += 256) {
        int l = i ^ j;
        if (l > i) {
          u64 a = fbuf[i], b2 = fbuf[l];
          bool up = ((i & k) == 0);
          if (up ? (a < b2) : (a > b2)) { fbuf[i] = b2; fbuf[l] = a; }
        }
      }
      __syncthreads();
    }
  }

  if (tid < 100) {
    u64 key = fbuf[tid];
    float s = __uint_as_float((u32)(key >> 32));
    int flat = (int)(0xFFFFFFFFu - (u32)key);
    if (flat < 0 || flat >= 8000) { flat = 0; s = 0.f; }  // guard (padding keys)
    float mlt = (s > 0.f) ? 1.f : 0.f;
    const float* bx = g_cls_b + ((size_t)b * 8000 + flat) * 4;
    out[(b * 100 + tid) * 4 + 0] = bx[0] * mlt;
    out[(b * 100 + tid) * 4 + 1] = bx[1] * mlt;
    out[(b * 100 + tid) * 4 + 2] = bx[2] * mlt;
    out[(b * 100 + tid) * 4 + 3] = bx[3] * mlt;
    out[6400 + b * 100 + tid] = (float)(flat / 100);
    out[8000 + b * 100 + tid] = s;
  }
}

// ---------------------------------------------------------------------------
extern "C" void kernel_launch(void* const* d_in, const int* in_sizes, int n_in,
                              void* d_out, int out_size) {
  const float* regs = (const float*)d_in[0];
  const float* ctrs = (const float*)d_in[1];
  const float* clfs = (const float*)d_in[2];
  for (int i = 0; i < n_in; i++) {
    if (in_sizes[i] == BBATCH * NN * 4) regs = (const float*)d_in[i];
    else if (in_sizes[i] == BBATCH * NN) ctrs = (const float*)d_in[i];
    else if (in_sizes[i] == BBATCH * NN * NCLS) clfs = (const float*)d_in[i];
  }
  float* out = (float*)d_out;

  dim3 gT(NN / 64, BBATCH);
  k_transpose<<<gT, 256>>>(clfs, ctrs);

  dim3 gS(NCLS, BBATCH);
  k_select<<<gS, 512>>>(regs, clfs, ctrs);

  k_final<<<BBATCH, 256>>>(out);
}